// round 6
// baseline (speedup 1.0000x reference)
#include <cuda_runtime.h>
#include <math.h>
#include <stdint.h>

// ---------------------------------------------------------------------------
// Problem constants
// ---------------------------------------------------------------------------
#define Nn 16            // B*T
#define Cc 512
#define Ss 1024          // H*W
#define NHEADS 8
#define HD 64
#define D3 1536          // 3*C

// ---------------------------------------------------------------------------
// Scratch (device globals; no cudaMalloc allowed)
// ---------------------------------------------------------------------------
__device__ float g_hn   [Nn * Ss * Cc];           // [n][s][c] tf32
__device__ float g_q    [Nn * NHEADS * Ss * HD];  // [nh][s][e] tf32
__device__ float g_k    [Nn * NHEADS * Ss * HD];  // [nh][s][e] tf32
__device__ float g_v    [Nn * NHEADS * HD * Ss];  // [nh][e][s] tf32
__device__ float g_att  [Nn * Ss * Cc];           // [n][s][c] tf32
__device__ float g_wqkvT[D3 * Cc];                // [d][c] tf32
__device__ float g_woutT[Cc * Cc];                // [c2][c] tf32

// ---------------------------------------------------------------------------
// Helpers
// ---------------------------------------------------------------------------
__device__ __forceinline__ uint32_t smem_u32(const void* p) {
    uint32_t a;
    asm("{ .reg .u64 t; cvta.to.shared.u64 t, %1; cvt.u32.u64 %0, t; }"
        : "=r"(a) : "l"(p));
    return a;
}

__device__ __forceinline__ float tf32r(float x) {
    uint32_t u;
    asm("cvt.rna.tf32.f32 %0, %1;" : "=r"(u) : "f"(x));
    return __uint_as_float(u);
}

// m16n8k8 tf32 mma, D = A*B + D (in place)
__device__ __forceinline__ void mma8(float* d, const uint32_t* a, const uint32_t* b) {
    asm volatile(
        "mma.sync.aligned.m16n8k8.row.col.f32.tf32.tf32.f32 "
        "{%0,%1,%2,%3}, {%4,%5,%6,%7}, {%8,%9}, {%0,%1,%2,%3};"
        : "+f"(d[0]), "+f"(d[1]), "+f"(d[2]), "+f"(d[3])
        : "r"(a[0]), "r"(a[1]), "r"(a[2]), "r"(a[3]), "r"(b[0]), "r"(b[1]));
}

// ldmatrix x4: four 8x8 b16 matrices == four 8x4 fp32 tiles, 4 regs/lane
__device__ __forceinline__ void ldsm4(uint32_t* r, uint32_t addr) {
    asm volatile("ldmatrix.sync.aligned.m8n8.x4.shared.b16 {%0,%1,%2,%3}, [%4];"
        : "=r"(r[0]), "=r"(r[1]), "=r"(r[2]), "=r"(r[3]) : "r"(addr));
}

__device__ __forceinline__ void cp16(uint32_t dst, const void* src) {
    asm volatile("cp.async.cg.shared.global [%0], [%1], 16;" :: "r"(dst), "l"(src));
}
#define CP_COMMIT() asm volatile("cp.async.commit_group;" ::: "memory")
#define CP_WAIT1()  asm volatile("cp.async.wait_group 1;" ::: "memory")

// ---------------------------------------------------------------------------
// Kernel 0: weight transpose + tf32 rounding   in [512][Ccols] -> out [Ccols][512]
// ---------------------------------------------------------------------------
__global__ void __launch_bounds__(256) trans_kernel(const float* __restrict__ in,
                                                    int Ccols, int which)
{
    float* out = which ? g_woutT : g_wqkvT;
    __shared__ float t[32][33];
    int c0 = blockIdx.x * 32, r0 = blockIdx.y * 32;
    int tx = threadIdx.x, ty = threadIdx.y;
#pragma unroll
    for (int i = 0; i < 32; i += 8)
        t[ty + i][tx] = in[(size_t)(r0 + ty + i) * Ccols + c0 + tx];
    __syncthreads();
#pragma unroll
    for (int i = 0; i < 32; i += 8)
        out[(size_t)(c0 + ty + i) * 512 + r0 + tx] = tf32r(t[tx][ty + i]);
}

// ---------------------------------------------------------------------------
// Kernel 1: GroupNorm (32 groups, eps=1e-6) -> g_hn [n][s][c] (tf32)
// ---------------------------------------------------------------------------
__global__ void __launch_bounds__(256) gn_kernel(const float* __restrict__ x,
                                                 const float* __restrict__ sc,
                                                 const float* __restrict__ bi)
{
    extern __shared__ float smt[];   // [1024][17]
    int n = blockIdx.x >> 5;
    int g = blockIdx.x & 31;
    const float* px = x + (size_t)(n * Cc + g * 16) * Ss;
    float* ph = g_hn + (size_t)n * Ss * Cc + g * 16;
    int tid = threadIdx.x;
    const int M = 16 * Ss;

    float s = 0.f, ss = 0.f;
    for (int i = tid * 4; i < M; i += 1024) {
        float4 v = *(const float4*)&px[i];
        s  += v.x + v.y + v.z + v.w;
        ss += v.x*v.x + v.y*v.y + v.z*v.z + v.w*v.w;
    }
#pragma unroll
    for (int o = 16; o; o >>= 1) {
        s  += __shfl_xor_sync(0xffffffffu, s,  o);
        ss += __shfl_xor_sync(0xffffffffu, ss, o);
    }
    __shared__ float r0[8], r1[8];
    __shared__ float s_mean, s_inv;
    if ((tid & 31) == 0) { r0[tid >> 5] = s; r1[tid >> 5] = ss; }
    __syncthreads();
    if (tid == 0) {
        float a = 0.f, b2 = 0.f;
#pragma unroll
        for (int i = 0; i < 8; i++) { a += r0[i]; b2 += r1[i]; }
        float mean = a / (float)M;
        float var  = b2 / (float)M - mean * mean;
        s_mean = mean;
        s_inv  = rsqrtf(var + 1e-6f);
    }
    __syncthreads();
    float mean = s_mean, inv = s_inv;

    for (int i = tid * 4; i < M; i += 1024) {
        int c  = i >> 10;
        int sp = i & 1023;
        float scv = sc[g * 16 + c] * inv;
        float biv = bi[g * 16 + c] - mean * scv;
        float4 v = *(const float4*)&px[i];
        smt[(sp + 0) * 17 + c] = tf32r(v.x * scv + biv);
        smt[(sp + 1) * 17 + c] = tf32r(v.y * scv + biv);
        smt[(sp + 2) * 17 + c] = tf32r(v.z * scv + biv);
        smt[(sp + 3) * 17 + c] = tf32r(v.w * scv + biv);
    }
    __syncthreads();

#pragma unroll
    for (int j = 0; j < 4; j++) {
        int sp = tid * 4 + j;
        const float* row = &smt[sp * 17];
        float* dst = ph + (size_t)sp * Cc;
#pragma unroll
        for (int q = 0; q < 4; q++) {
            float4 o = make_float4(row[q*4+0], row[q*4+1], row[q*4+2], row[q*4+3]);
            *(float4*)&dst[q * 4] = o;
        }
    }
}

// ---------------------------------------------------------------------------
// Kernel 2: tf32 mma.sync GEMM, tile 128x128, K=512, BK=32, 3-stage cp.async,
// ldmatrix fragment loads. 8 warps = 4(M) x 2(N), warp 32x64.
// ---------------------------------------------------------------------------
__device__ __forceinline__ void gemm_load(uint32_t sbase, int soff,
                                          const float* __restrict__ Ag,
                                          const float* __restrict__ Bg,
                                          int koff, int tid)
{
#pragma unroll
    for (int i = 0; i < 4; i++) {
        int f = tid + i * 256;
        int row = f >> 3, c4 = f & 7;
        cp16(sbase + (uint32_t)((soff + row * 36 + c4 * 4) * 4),
             Ag + (size_t)row * Cc + koff + c4 * 4);
        cp16(sbase + (uint32_t)((soff + 4608 + row * 36 + c4 * 4) * 4),
             Bg + (size_t)row * Cc + koff + c4 * 4);
    }
}

__global__ void __launch_bounds__(256, 2) gemm_mma(const float* __restrict__ bias,
                                                   const float* __restrict__ xres,
                                                   float* __restrict__ out,
                                                   int mode)
{
    extern __shared__ float sm[];
    uint32_t sbase = smem_u32(sm);
    int tid = threadIdx.x, lane = tid & 31, wid = tid >> 5;
    int g = lane >> 2, tg = lane & 3;
    int n = blockIdx.z, s0 = blockIdx.x * 128, d0 = blockIdx.y * 128;
    int wm = wid & 3, wn = wid >> 2;

    const float* Ag = (mode ? g_att : g_hn) + ((size_t)n * Ss + s0) * Cc;
    const float* Bg = (mode ? g_woutT : g_wqkvT) + (size_t)d0 * Cc;

    // ldmatrix lane addressing
    int matq = lane >> 3, mr = lane & 7;
    // A: mat -> rowsub=(matq&1)*8, koff=(matq>>1)*4
    uint32_t aBase = sbase + (uint32_t)(((wm * 32 + (matq & 1) * 8 + mr) * 36
                                        + (matq >> 1) * 4) * 4);
    // B: mat -> rowsub=(matq>>1)*8, koff=(matq&1)*4
    uint32_t bBase = sbase + (uint32_t)((4608 + (wn * 64 + (matq >> 1) * 8 + mr) * 36
                                        + (matq & 1) * 4) * 4);

    float C[2][8][4] = {};

    gemm_load(sbase, 0, Ag, Bg, 0, tid);
    CP_COMMIT();
    gemm_load(sbase, 9216, Ag, Bg, 32, tid);
    CP_COMMIT();

    for (int kc = 0; kc < 16; kc++) {
        CP_WAIT1();
        __syncthreads();
        int b = kc % 3;
        if (kc + 2 < 16)
            gemm_load(sbase, ((kc + 2) % 3) * 9216, Ag, Bg, (kc + 2) * 32, tid);
        CP_COMMIT();

        uint32_t sA = aBase + (uint32_t)(b * 9216 * 4);
        uint32_t sB = bBase + (uint32_t)(b * 9216 * 4);
#pragma unroll
        for (int ks = 0; ks < 4; ks++) {
            uint32_t a0[4], a1[4];
            ldsm4(a0, sA + ks * 32);
            ldsm4(a1, sA + ks * 32 + 16 * 36 * 4);
#pragma unroll
            for (int tp = 0; tp < 4; tp++) {
                uint32_t bf[4];
                ldsm4(bf, sB + ks * 32 + tp * 16 * 36 * 4);
                mma8(C[0][2 * tp],     a0, bf);
                mma8(C[1][2 * tp],     a1, bf);
                mma8(C[0][2 * tp + 1], a0, bf + 2);
                mma8(C[1][2 * tp + 1], a1, bf + 2);
            }
        }
    }

    // epilogue
#pragma unroll
    for (int tm = 0; tm < 2; tm++) {
#pragma unroll
        for (int hh = 0; hh < 2; hh++) {
            int m = s0 + wm * 32 + tm * 16 + g + hh * 8;
#pragma unroll
            for (int tn = 0; tn < 8; tn++) {
                int d = d0 + wn * 64 + tn * 8 + 2 * tg;
                float v0 = C[tm][tn][hh * 2 + 0] + __ldg(&bias[d]);
                float v1 = C[tm][tn][hh * 2 + 1] + __ldg(&bias[d + 1]);
                if (mode == 0) {
                    int head = d / 192, t = d % 192;
                    int part = t >> 6, e = t & 63;
                    size_t nh = (size_t)(n * 8 + head);
                    if (part == 0) {
                        float2 val = make_float2(tf32r(v0), tf32r(v1));
                        *(float2*)&g_q[(nh * Ss + m) * HD + e] = val;
                    } else if (part == 1) {
                        float2 val = make_float2(tf32r(v0), tf32r(v1));
                        *(float2*)&g_k[(nh * Ss + m) * HD + e] = val;
                    } else {
                        g_v[(nh * HD + e) * Ss + m]     = tf32r(v0);
                        g_v[(nh * HD + e + 1) * Ss + m] = tf32r(v1);
                    }
                } else {
                    size_t gi = ((size_t)n * Cc + d) * Ss + m;
                    out[gi]      = v0 + xres[gi];
                    out[gi + Ss] = v1 + xres[gi + Ss];
                }
            }
        }
    }
}

// ---------------------------------------------------------------------------
// Kernel 3: flash attention, tf32 mma.sync, double-buffered cp.async K/V,
// ldmatrix fragment loads, shuffle-transposed P (no smem round trip).
// SMEM floats: KV stage b: K at b*8704, V at b*8704+4352; Q at 17408.
// ---------------------------------------------------------------------------
#define ATT_SMEM 104448

__device__ __forceinline__ void attn_load_kv(uint32_t sbase, int b,
                                             const float* __restrict__ K,
                                             const float* __restrict__ V,
                                             int kt, int tid)
{
#pragma unroll
    for (int i = 0; i < 4; i++) {
        int f = tid + i * 256;
        int r = f >> 4, c4 = f & 15;
        cp16(sbase + (uint32_t)((b * 8704 + r * 68 + c4 * 4) * 4),
             K + (size_t)(kt * 64 + r) * HD + c4 * 4);
        cp16(sbase + (uint32_t)((b * 8704 + 4352 + r * 68 + c4 * 4) * 4),
             V + (size_t)r * Ss + kt * 64 + c4 * 4);
    }
}

__global__ void __launch_bounds__(256, 2) attn_mma()
{
    extern __shared__ float sm[];
    uint32_t sbase = smem_u32(sm);

    int tid = threadIdx.x, lane = tid & 31, w = tid >> 5;
    int g = lane >> 2, tg = lane & 3;
    int nh = blockIdx.y, q0 = blockIdx.x * 128;
    const float* Q = g_q + (size_t)nh * Ss * HD;
    const float* K = g_k + (size_t)nh * Ss * HD;
    const float* V = g_v + (size_t)nh * HD * Ss;

    // ldmatrix lane addressing
    int matq = lane >> 3, mr = lane & 7;
    int qb = w * 16;
    // Q frag (A): rowsub=(matq&1)*8, koff=(matq>>1)*4 ; region at 17408, stride 68
    uint32_t qAddr = sbase + (uint32_t)((17408 + (qb + (matq & 1) * 8 + mr) * 68
                                        + (matq >> 1) * 4) * 4);
    // K/V frags (B): rowsub=(matq>>1)*8, koff=(matq&1)*4 ; stride 68
    uint32_t kvBase = (uint32_t)((((matq >> 1) * 8 + mr) * 68 + (matq & 1) * 4) * 4);

    // prologue: Q + KV(0) -> group 0; KV(1) -> group 1
#pragma unroll
    for (int i = 0; i < 8; i++) {
        int f = tid + i * 256;
        int row = f >> 4, c4 = f & 15;
        cp16(sbase + (uint32_t)((17408 + row * 68 + c4 * 4) * 4),
             Q + (size_t)(q0 + row) * HD + c4 * 4);
    }
    attn_load_kv(sbase, 0, K, V, 0, tid);
    CP_COMMIT();
    attn_load_kv(sbase, 1, K, V, 1, tid);
    CP_COMMIT();

    float O[8][4] = {};
    float m0 = -1e30f, m1 = -1e30f, l0 = 0.f, l1 = 0.f;
    int srcA = g * 4 + (tg >> 1);
    int srcB = srcA + 2;
    bool oddc = (tg & 1);

    for (int kt = 0; kt < 16; kt++) {
        CP_WAIT1();
        __syncthreads();
        int b = kt & 1;
        uint32_t kAddr = sbase + (uint32_t)(b * 8704 * 4) + kvBase;
        uint32_t vAddr = kAddr + (uint32_t)(4352 * 4);

        // S = Q @ K^T  (warp: 16 q rows x 64 keys), k-dim = e (64 -> 8 steps)
        float S[8][4] = {};
#pragma unroll
        for (int ks = 0; ks < 8; ks++) {
            uint32_t a[4];
            ldsm4(a, qAddr + ks * 32);
#pragma unroll
            for (int tp = 0; tp < 4; tp++) {
                uint32_t bf[4];
                ldsm4(bf, kAddr + ks * 32 + tp * 16 * 68 * 4);
                mma8(S[2 * tp],     a, bf);
                mma8(S[2 * tp + 1], a, bf + 2);
            }
        }

        // scale + online softmax
        float mx0 = -1e30f, mx1 = -1e30f;
#pragma unroll
        for (int tn = 0; tn < 8; tn++) {
            S[tn][0] *= 0.125f; S[tn][1] *= 0.125f;
            S[tn][2] *= 0.125f; S[tn][3] *= 0.125f;
            mx0 = fmaxf(mx0, fmaxf(S[tn][0], S[tn][1]));
            mx1 = fmaxf(mx1, fmaxf(S[tn][2], S[tn][3]));
        }
        mx0 = fmaxf(mx0, __shfl_xor_sync(0xffffffffu, mx0, 1));
        mx0 = fmaxf(mx0, __shfl_xor_sync(0xffffffffu, mx0, 2));
        mx1 = fmaxf(mx1, __shfl_xor_sync(0xffffffffu, mx1, 1));
        mx1 = fmaxf(mx1, __shfl_xor_sync(0xffffffffu, mx1, 2));
        float mn0 = fmaxf(m0, mx0), mn1 = fmaxf(m1, mx1);
        float cr0 = __expf(m0 - mn0), cr1 = __expf(m1 - mn1);
        float rs0 = 0.f, rs1 = 0.f;
#pragma unroll
        for (int tn = 0; tn < 8; tn++) {
            S[tn][0] = tf32r(__expf(S[tn][0] - mn0));
            S[tn][1] = tf32r(__expf(S[tn][1] - mn0));
            S[tn][2] = tf32r(__expf(S[tn][2] - mn1));
            S[tn][3] = tf32r(__expf(S[tn][3] - mn1));
            rs0 += S[tn][0] + S[tn][1];
            rs1 += S[tn][2] + S[tn][3];
        }
        rs0 += __shfl_xor_sync(0xffffffffu, rs0, 1);
        rs0 += __shfl_xor_sync(0xffffffffu, rs0, 2);
        rs1 += __shfl_xor_sync(0xffffffffu, rs1, 1);
        rs1 += __shfl_xor_sync(0xffffffffu, rs1, 2);
        l0 = l0 * cr0 + rs0;  l1 = l1 * cr1 + rs1;
        m0 = mn0;  m1 = mn1;

#pragma unroll
        for (int tn = 0; tn < 8; tn++) {
            O[tn][0] *= cr0; O[tn][1] *= cr0;
            O[tn][2] *= cr1; O[tn][3] *= cr1;
        }

        // O += P @ V : P a-frags via quad shuffles, V b-frags via ldmatrix
#pragma unroll
        for (int ks = 0; ks < 8; ks++) {
            float e00 = __shfl_sync(0xffffffffu, S[ks][0], srcA);
            float e01 = __shfl_sync(0xffffffffu, S[ks][1], srcA);
            float e10 = __shfl_sync(0xffffffffu, S[ks][2], srcA);
            float e11 = __shfl_sync(0xffffffffu, S[ks][3], srcA);
            float f00 = __shfl_sync(0xffffffffu, S[ks][0], srcB);
            float f01 = __shfl_sync(0xffffffffu, S[ks][1], srcB);
            float f10 = __shfl_sync(0xffffffffu, S[ks][2], srcB);
            float f11 = __shfl_sync(0xffffffffu, S[ks][3], srcB);
            uint32_t a[4];
            a[0] = __float_as_uint(oddc ? e01 : e00);
            a[1] = __float_as_uint(oddc ? e11 : e10);
            a[2] = __float_as_uint(oddc ? f01 : f00);
            a[3] = __float_as_uint(oddc ? f11 : f10);
#pragma unroll
            for (int tp = 0; tp < 4; tp++) {
                uint32_t bf[4];
                ldsm4(bf, vAddr + ks * 32 + tp * 16 * 68 * 4);
                mma8(O[2 * tp],     a, bf);
                mma8(O[2 * tp + 1], a, bf + 2);
            }
        }

        __syncthreads();
        if (kt + 2 < 16)
            attn_load_kv(sbase, b, K, V, kt + 2, tid);
        CP_COMMIT();
    }

    // epilogue -> g_att[n][s][head*64 + e], tf32-rounded
    int n = nh >> 3, head = nh & 7;
    float inv0 = 1.f / l0, inv1 = 1.f / l1;
    int srow0 = q0 + qb + g, srow1 = srow0 + 8;
    float* dst = g_att + (size_t)n * Ss * Cc + head * 64;
#pragma unroll
    for (int tn = 0; tn < 8; tn++) {
        int c = tn * 8 + 2 * tg;
        float2 v0 = make_float2(tf32r(O[tn][0] * inv0), tf32r(O[tn][1] * inv0));
        float2 v1 = make_float2(tf32r(O[tn][2] * inv1), tf32r(O[tn][3] * inv1));
        *(float2*)&dst[(size_t)srow0 * Cc + c] = v0;
        *(float2*)&dst[(size_t)srow1 * Cc + c] = v1;
    }
}

// ---------------------------------------------------------------------------
extern "C" void kernel_launch(void* const* d_in, const int* in_sizes, int n_in,
                              void* d_out, int out_size)
{
    const float* x    = (const float*)d_in[0];
    const float* gsc  = (const float*)d_in[1];
    const float* gbi  = (const float*)d_in[2];
    const float* wqkv = (const float*)d_in[3];
    const float* bqkv = (const float*)d_in[4];
    const float* wout = (const float*)d_in[5];
    const float* bout = (const float*)d_in[6];
    float* out = (float*)d_out;

    trans_kernel<<<dim3(D3 / 32, Cc / 32), dim3(32, 8)>>>(wqkv, D3, 0);
    trans_kernel<<<dim3(Cc / 32, Cc / 32), dim3(32, 8)>>>(wout, Cc, 1);

    cudaFuncSetAttribute(gn_kernel, cudaFuncAttributeMaxDynamicSharedMemorySize, 69632);
    gn_kernel<<<Nn * 32, 256, 69632>>>(x, gsc, gbi);

    const int gemm_smem = 27648 * 4;   // 3 stages x 9216 floats
    cudaFuncSetAttribute(gemm_mma, cudaFuncAttributeMaxDynamicSharedMemorySize, gemm_smem);
    gemm_mma<<<dim3(Ss / 128, D3 / 128, Nn), 256, gemm_smem>>>(bqkv, nullptr, nullptr, 0);

    cudaFuncSetAttribute(attn_mma, cudaFuncAttributeMaxDynamicSharedMemorySize, ATT_SMEM);
    attn_mma<<<dim3(Ss / 128, Nn * NHEADS), 256, ATT_SMEM>>>();

    gemm_mma<<<dim3(Ss / 128, Cc / 128, Nn), 256, gemm_smem>>>(bout, x, out, 1);
}

// round 7
// speedup vs baseline: 1.4181x; 1.4181x over previous
#include <cuda_runtime.h>
#include <math.h>
#include <stdint.h>

// ---------------------------------------------------------------------------
// Problem constants
// ---------------------------------------------------------------------------
#define Nn 16            // B*T
#define Cc 512
#define Ss 1024          // H*W
#define NHEADS 8
#define HD 64
#define D3 1536          // 3*C

// ---------------------------------------------------------------------------
// Scratch (device globals; no cudaMalloc allowed)
// ---------------------------------------------------------------------------
__device__ float g_hn   [Nn * Ss * Cc];           // [n][s][c] tf32
__device__ float g_q    [Nn * NHEADS * Ss * HD];  // [nh][s][e] tf32
__device__ float g_k    [Nn * NHEADS * Ss * HD];  // [nh][s][e] tf32
__device__ float g_v    [Nn * NHEADS * HD * Ss];  // [nh][e][s] tf32
__device__ float g_att  [Nn * Ss * Cc];           // [n][s][c] tf32
__device__ float g_wqkvT[D3 * Cc];                // [d][c] tf32
__device__ float g_woutT[Cc * Cc];                // [c2][c] tf32

// ---------------------------------------------------------------------------
// Helpers
// ---------------------------------------------------------------------------
__device__ __forceinline__ uint32_t smem_u32(const void* p) {
    uint32_t a;
    asm("{ .reg .u64 t; cvta.to.shared.u64 t, %1; cvt.u32.u64 %0, t; }"
        : "=r"(a) : "l"(p));
    return a;
}

__device__ __forceinline__ float tf32r(float x) {
    uint32_t u;
    asm("cvt.rna.tf32.f32 %0, %1;" : "=r"(u) : "f"(x));
    return __uint_as_float(u);
}

// m16n8k8 tf32 mma, D = A*B + D (in place)
__device__ __forceinline__ void mma8(float* d, const uint32_t* a, const uint32_t* b) {
    asm volatile(
        "mma.sync.aligned.m16n8k8.row.col.f32.tf32.tf32.f32 "
        "{%0,%1,%2,%3}, {%4,%5,%6,%7}, {%8,%9}, {%0,%1,%2,%3};"
        : "+f"(d[0]), "+f"(d[1]), "+f"(d[2]), "+f"(d[3])
        : "r"(a[0]), "r"(a[1]), "r"(a[2]), "r"(a[3]), "r"(b[0]), "r"(b[1]));
}

__device__ __forceinline__ void cp16(uint32_t dst, const void* src) {
    asm volatile("cp.async.cg.shared.global [%0], [%1], 16;" :: "r"(dst), "l"(src));
}
#define CP_COMMIT() asm volatile("cp.async.commit_group;" ::: "memory")
#define CP_WAIT1()  asm volatile("cp.async.wait_group 1;" ::: "memory")

// ---------------------------------------------------------------------------
// Kernel 0: weight transpose + tf32 rounding   in [512][Ccols] -> out [Ccols][512]
// ---------------------------------------------------------------------------
__global__ void __launch_bounds__(256) trans_kernel(const float* __restrict__ in,
                                                    int Ccols, int which)
{
    float* out = which ? g_woutT : g_wqkvT;
    __shared__ float t[32][33];
    int c0 = blockIdx.x * 32, r0 = blockIdx.y * 32;
    int tx = threadIdx.x, ty = threadIdx.y;
#pragma unroll
    for (int i = 0; i < 32; i += 8)
        t[ty + i][tx] = in[(size_t)(r0 + ty + i) * Ccols + c0 + tx];
    __syncthreads();
#pragma unroll
    for (int i = 0; i < 32; i += 8)
        out[(size_t)(c0 + ty + i) * 512 + r0 + tx] = tf32r(t[tx][ty + i]);
}

// ---------------------------------------------------------------------------
// Kernel 1: GroupNorm (32 groups, eps=1e-6) -> g_hn [n][s][c] (tf32)
// ---------------------------------------------------------------------------
__global__ void __launch_bounds__(256) gn_kernel(const float* __restrict__ x,
                                                 const float* __restrict__ sc,
                                                 const float* __restrict__ bi)
{
    extern __shared__ float smt[];   // [1024][17]
    int n = blockIdx.x >> 5;
    int g = blockIdx.x & 31;
    const float* px = x + (size_t)(n * Cc + g * 16) * Ss;
    float* ph = g_hn + (size_t)n * Ss * Cc + g * 16;
    int tid = threadIdx.x;
    const int M = 16 * Ss;

    float s = 0.f, ss = 0.f;
    for (int i = tid * 4; i < M; i += 1024) {
        float4 v = *(const float4*)&px[i];
        s  += v.x + v.y + v.z + v.w;
        ss += v.x*v.x + v.y*v.y + v.z*v.z + v.w*v.w;
    }
#pragma unroll
    for (int o = 16; o; o >>= 1) {
        s  += __shfl_xor_sync(0xffffffffu, s,  o);
        ss += __shfl_xor_sync(0xffffffffu, ss, o);
    }
    __shared__ float r0[8], r1[8];
    __shared__ float s_mean, s_inv;
    if ((tid & 31) == 0) { r0[tid >> 5] = s; r1[tid >> 5] = ss; }
    __syncthreads();
    if (tid == 0) {
        float a = 0.f, b2 = 0.f;
#pragma unroll
        for (int i = 0; i < 8; i++) { a += r0[i]; b2 += r1[i]; }
        float mean = a / (float)M;
        float var  = b2 / (float)M - mean * mean;
        s_mean = mean;
        s_inv  = rsqrtf(var + 1e-6f);
    }
    __syncthreads();
    float mean = s_mean, inv = s_inv;

    for (int i = tid * 4; i < M; i += 1024) {
        int c  = i >> 10;
        int sp = i & 1023;
        float scv = sc[g * 16 + c] * inv;
        float biv = bi[g * 16 + c] - mean * scv;
        float4 v = *(const float4*)&px[i];
        smt[(sp + 0) * 17 + c] = tf32r(v.x * scv + biv);
        smt[(sp + 1) * 17 + c] = tf32r(v.y * scv + biv);
        smt[(sp + 2) * 17 + c] = tf32r(v.z * scv + biv);
        smt[(sp + 3) * 17 + c] = tf32r(v.w * scv + biv);
    }
    __syncthreads();

#pragma unroll
    for (int j = 0; j < 4; j++) {
        int sp = tid * 4 + j;
        const float* row = &smt[sp * 17];
        float* dst = ph + (size_t)sp * Cc;
#pragma unroll
        for (int q = 0; q < 4; q++) {
            float4 o = make_float4(row[q*4+0], row[q*4+1], row[q*4+2], row[q*4+3]);
            *(float4*)&dst[q * 4] = o;
        }
    }
}

// ---------------------------------------------------------------------------
// Kernel 2: tf32 mma.sync GEMM, tile 128x128, K=512, BK=32, 3-stage cp.async.
// 512 threads = 16 warps as 4(M) x 4(N); warp tile 32x32 -> 32 accum regs,
// forced <=64 regs so 2 CTAs/SM = 32 warps/SM (occupancy ~48%).
// SMEM stride 36 floats => conflict-free fragment loads.
// ---------------------------------------------------------------------------
__device__ __forceinline__ void gemm_load(uint32_t sbase, int soff,
                                          const float* __restrict__ Ag,
                                          const float* __restrict__ Bg,
                                          int koff, int tid)
{
#pragma unroll
    for (int i = 0; i < 2; i++) {
        int f = tid + i * 512;
        int row = f >> 3, c4 = f & 7;
        cp16(sbase + (uint32_t)((soff + row * 36 + c4 * 4) * 4),
             Ag + (size_t)row * Cc + koff + c4 * 4);
        cp16(sbase + (uint32_t)((soff + 4608 + row * 36 + c4 * 4) * 4),
             Bg + (size_t)row * Cc + koff + c4 * 4);
    }
}

__global__ void __launch_bounds__(512, 2) gemm_mma(const float* __restrict__ bias,
                                                   const float* __restrict__ xres,
                                                   float* __restrict__ out,
                                                   int mode)
{
    extern __shared__ float sm[];
    uint32_t sbase = smem_u32(sm);
    int tid = threadIdx.x, lane = tid & 31, wid = tid >> 5;
    int g = lane >> 2, tg = lane & 3;
    int n = blockIdx.z, s0 = blockIdx.x * 128, d0 = blockIdx.y * 128;
    int wm = wid & 3, wn = wid >> 2;

    const float* Ag = (mode ? g_att : g_hn) + ((size_t)n * Ss + s0) * Cc;
    const float* Bg = (mode ? g_woutT : g_wqkvT) + (size_t)d0 * Cc;

    float C[2][4][4] = {};

    gemm_load(sbase, 0, Ag, Bg, 0, tid);
    CP_COMMIT();
    gemm_load(sbase, 9216, Ag, Bg, 32, tid);
    CP_COMMIT();

    for (int kc = 0; kc < 16; kc++) {
        CP_WAIT1();
        __syncthreads();
        int b = kc % 3;
        if (kc + 2 < 16)
            gemm_load(sbase, ((kc + 2) % 3) * 9216, Ag, Bg, (kc + 2) * 32, tid);
        CP_COMMIT();

        const float* As = sm + b * 9216;
        const float* Bs = As + 4608;
#pragma unroll
        for (int ks = 0; ks < 4; ks++) {
            int k0 = ks * 8;
            uint32_t a[2][4], bb[4][2];
#pragma unroll
            for (int tm = 0; tm < 2; tm++) {
                int r = wm * 32 + tm * 16 + g;
                a[tm][0] = __float_as_uint(As[r * 36 + k0 + tg]);
                a[tm][1] = __float_as_uint(As[(r + 8) * 36 + k0 + tg]);
                a[tm][2] = __float_as_uint(As[r * 36 + k0 + tg + 4]);
                a[tm][3] = __float_as_uint(As[(r + 8) * 36 + k0 + tg + 4]);
            }
#pragma unroll
            for (int tn = 0; tn < 4; tn++) {
                int c = wn * 32 + tn * 8 + g;
                bb[tn][0] = __float_as_uint(Bs[c * 36 + k0 + tg]);
                bb[tn][1] = __float_as_uint(Bs[c * 36 + k0 + tg + 4]);
            }
#pragma unroll
            for (int tm = 0; tm < 2; tm++)
#pragma unroll
                for (int tn = 0; tn < 4; tn++)
                    mma8(C[tm][tn], a[tm], bb[tn]);
        }
    }

    // epilogue
#pragma unroll
    for (int tm = 0; tm < 2; tm++) {
#pragma unroll
        for (int hh = 0; hh < 2; hh++) {
            int m = s0 + wm * 32 + tm * 16 + g + hh * 8;
#pragma unroll
            for (int tn = 0; tn < 4; tn++) {
                int d = d0 + wn * 32 + tn * 8 + 2 * tg;
                float v0 = C[tm][tn][hh * 2 + 0] + __ldg(&bias[d]);
                float v1 = C[tm][tn][hh * 2 + 1] + __ldg(&bias[d + 1]);
                if (mode == 0) {
                    int head = d / 192, t = d % 192;
                    int part = t >> 6, e = t & 63;
                    size_t nh = (size_t)(n * 8 + head);
                    if (part == 0) {
                        float2 val = make_float2(tf32r(v0), tf32r(v1));
                        *(float2*)&g_q[(nh * Ss + m) * HD + e] = val;
                    } else if (part == 1) {
                        float2 val = make_float2(tf32r(v0), tf32r(v1));
                        *(float2*)&g_k[(nh * Ss + m) * HD + e] = val;
                    } else {
                        g_v[(nh * HD + e) * Ss + m]     = tf32r(v0);
                        g_v[(nh * HD + e + 1) * Ss + m] = tf32r(v1);
                    }
                } else {
                    size_t gi = ((size_t)n * Cc + d) * Ss + m;
                    out[gi]      = v0 + xres[gi];
                    out[gi + Ss] = v1 + xres[gi + Ss];
                }
            }
        }
    }
}

// ---------------------------------------------------------------------------
// Kernel 3: flash attention, tf32 mma.sync, double-buffered cp.async K/V,
// register shuffle-transpose for P (no smem round trip).  (R4 verbatim)
// SMEM floats: KV stage b: K at b*8704, V at b*8704+4352; Q at 17408.
// ---------------------------------------------------------------------------
#define ATT_SMEM 104448

__device__ __forceinline__ void attn_load_kv(uint32_t sbase, int b,
                                             const float* __restrict__ K,
                                             const float* __restrict__ V,
                                             int kt, int tid)
{
#pragma unroll
    for (int i = 0; i < 4; i++) {
        int f = tid + i * 256;
        int r = f >> 4, c4 = f & 15;
        cp16(sbase + (uint32_t)((b * 8704 + r * 68 + c4 * 4) * 4),
             K + (size_t)(kt * 64 + r) * HD + c4 * 4);
        cp16(sbase + (uint32_t)((b * 8704 + 4352 + r * 68 + c4 * 4) * 4),
             V + (size_t)r * Ss + kt * 64 + c4 * 4);
    }
}

__global__ void __launch_bounds__(256, 2) attn_mma()
{
    extern __shared__ float sm[];
    uint32_t sbase = smem_u32(sm);
    float* Qs = sm + 17408;

    int tid = threadIdx.x, lane = tid & 31, w = tid >> 5;
    int g = lane >> 2, tg = lane & 3;
    int nh = blockIdx.y, q0 = blockIdx.x * 128;
    const float* Q = g_q + (size_t)nh * Ss * HD;
    const float* K = g_k + (size_t)nh * Ss * HD;
    const float* V = g_v + (size_t)nh * HD * Ss;

    // prologue: Q + KV(0) -> group 0; KV(1) -> group 1
#pragma unroll
    for (int i = 0; i < 8; i++) {
        int f = tid + i * 256;
        int row = f >> 4, c4 = f & 15;
        cp16(sbase + (uint32_t)((17408 + row * 68 + c4 * 4) * 4),
             Q + (size_t)(q0 + row) * HD + c4 * 4);
    }
    attn_load_kv(sbase, 0, K, V, 0, tid);
    CP_COMMIT();
    attn_load_kv(sbase, 1, K, V, 1, tid);
    CP_COMMIT();

    float O[8][4] = {};
    float m0 = -1e30f, m1 = -1e30f, l0 = 0.f, l1 = 0.f;
    int qb = w * 16;
    int srcA = g * 4 + (tg >> 1);
    int srcB = srcA + 2;
    bool oddc = (tg & 1);

    for (int kt = 0; kt < 16; kt++) {
        CP_WAIT1();
        __syncthreads();
        int b = kt & 1;
        const float* Ks = sm + b * 8704;
        const float* Vs = Ks + 4352;

        // S = Q @ K^T
        float S[8][4] = {};
#pragma unroll
        for (int ks = 0; ks < 8; ks++) {
            int k0 = ks * 8;
            uint32_t a[4];
            a[0] = __float_as_uint(Qs[(qb + g) * 68 + k0 + tg]);
            a[1] = __float_as_uint(Qs[(qb + g + 8) * 68 + k0 + tg]);
            a[2] = __float_as_uint(Qs[(qb + g) * 68 + k0 + tg + 4]);
            a[3] = __float_as_uint(Qs[(qb + g + 8) * 68 + k0 + tg + 4]);
#pragma unroll
            for (int tn = 0; tn < 8; tn++) {
                uint32_t bfr[2];
                bfr[0] = __float_as_uint(Ks[(tn * 8 + g) * 68 + k0 + tg]);
                bfr[1] = __float_as_uint(Ks[(tn * 8 + g) * 68 + k0 + tg + 4]);
                mma8(S[tn], a, bfr);
            }
        }

        // scale + online softmax
        float mx0 = -1e30f, mx1 = -1e30f;
#pragma unroll
        for (int tn = 0; tn < 8; tn++) {
            S[tn][0] *= 0.125f; S[tn][1] *= 0.125f;
            S[tn][2] *= 0.125f; S[tn][3] *= 0.125f;
            mx0 = fmaxf(mx0, fmaxf(S[tn][0], S[tn][1]));
            mx1 = fmaxf(mx1, fmaxf(S[tn][2], S[tn][3]));
        }
        mx0 = fmaxf(mx0, __shfl_xor_sync(0xffffffffu, mx0, 1));
        mx0 = fmaxf(mx0, __shfl_xor_sync(0xffffffffu, mx0, 2));
        mx1 = fmaxf(mx1, __shfl_xor_sync(0xffffffffu, mx1, 1));
        mx1 = fmaxf(mx1, __shfl_xor_sync(0xffffffffu, mx1, 2));
        float mn0 = fmaxf(m0, mx0), mn1 = fmaxf(m1, mx1);
        float cr0 = __expf(m0 - mn0), cr1 = __expf(m1 - mn1);
        float rs0 = 0.f, rs1 = 0.f;
#pragma unroll
        for (int tn = 0; tn < 8; tn++) {
            S[tn][0] = tf32r(__expf(S[tn][0] - mn0));
            S[tn][1] = tf32r(__expf(S[tn][1] - mn0));
            S[tn][2] = tf32r(__expf(S[tn][2] - mn1));
            S[tn][3] = tf32r(__expf(S[tn][3] - mn1));
            rs0 += S[tn][0] + S[tn][1];
            rs1 += S[tn][2] + S[tn][3];
        }
        rs0 += __shfl_xor_sync(0xffffffffu, rs0, 1);
        rs0 += __shfl_xor_sync(0xffffffffu, rs0, 2);
        rs1 += __shfl_xor_sync(0xffffffffu, rs1, 1);
        rs1 += __shfl_xor_sync(0xffffffffu, rs1, 2);
        l0 = l0 * cr0 + rs0;  l1 = l1 * cr1 + rs1;
        m0 = mn0;  m1 = mn1;

#pragma unroll
        for (int tn = 0; tn < 8; tn++) {
            O[tn][0] *= cr0; O[tn][1] *= cr0;
            O[tn][2] *= cr1; O[tn][3] *= cr1;
        }

        // O += P @ V (P a-frags via quad shuffles)
#pragma unroll
        for (int ks = 0; ks < 8; ks++) {
            float e00 = __shfl_sync(0xffffffffu, S[ks][0], srcA);
            float e01 = __shfl_sync(0xffffffffu, S[ks][1], srcA);
            float e10 = __shfl_sync(0xffffffffu, S[ks][2], srcA);
            float e11 = __shfl_sync(0xffffffffu, S[ks][3], srcA);
            float f00 = __shfl_sync(0xffffffffu, S[ks][0], srcB);
            float f01 = __shfl_sync(0xffffffffu, S[ks][1], srcB);
            float f10 = __shfl_sync(0xffffffffu, S[ks][2], srcB);
            float f11 = __shfl_sync(0xffffffffu, S[ks][3], srcB);
            uint32_t a[4];
            a[0] = __float_as_uint(oddc ? e01 : e00);
            a[1] = __float_as_uint(oddc ? e11 : e10);
            a[2] = __float_as_uint(oddc ? f01 : f00);
            a[3] = __float_as_uint(oddc ? f11 : f10);
            int k0 = ks * 8;
#pragma unroll
            for (int tn = 0; tn < 8; tn++) {
                uint32_t bfr[2];
                bfr[0] = __float_as_uint(Vs[(tn * 8 + g) * 68 + k0 + tg]);
                bfr[1] = __float_as_uint(Vs[(tn * 8 + g) * 68 + k0 + tg + 4]);
                mma8(O[tn], a, bfr);
            }
        }

        __syncthreads();
        if (kt + 2 < 16)
            attn_load_kv(sbase, b, K, V, kt + 2, tid);
        CP_COMMIT();
    }

    // epilogue -> g_att[n][s][head*64 + e], tf32-rounded
    int n = nh >> 3, head = nh & 7;
    float inv0 = 1.f / l0, inv1 = 1.f / l1;
    int srow0 = q0 + qb + g, srow1 = srow0 + 8;
    float* dst = g_att + (size_t)n * Ss * Cc + head * 64;
#pragma unroll
    for (int tn = 0; tn < 8; tn++) {
        int c = tn * 8 + 2 * tg;
        float2 v0 = make_float2(tf32r(O[tn][0] * inv0), tf32r(O[tn][1] * inv0));
        float2 v1 = make_float2(tf32r(O[tn][2] * inv1), tf32r(O[tn][3] * inv1));
        *(float2*)&dst[(size_t)srow0 * Cc + c] = v0;
        *(float2*)&dst[(size_t)srow1 * Cc + c] = v1;
    }
}

// ---------------------------------------------------------------------------
extern "C" void kernel_launch(void* const* d_in, const int* in_sizes, int n_in,
                              void* d_out, int out_size)
{
    const float* x    = (const float*)d_in[0];
    const float* gsc  = (const float*)d_in[1];
    const float* gbi  = (const float*)d_in[2];
    const float* wqkv = (const float*)d_in[3];
    const float* bqkv = (const float*)d_in[4];
    const float* wout = (const float*)d_in[5];
    const float* bout = (const float*)d_in[6];
    float* out = (float*)d_out;

    trans_kernel<<<dim3(D3 / 32, Cc / 32), dim3(32, 8)>>>(wqkv, D3, 0);
    trans_kernel<<<dim3(Cc / 32, Cc / 32), dim3(32, 8)>>>(wout, Cc, 1);

    cudaFuncSetAttribute(gn_kernel, cudaFuncAttributeMaxDynamicSharedMemorySize, 69632);
    gn_kernel<<<Nn * 32, 256, 69632>>>(x, gsc, gbi);

    const int gemm_smem = 27648 * 4;   // 3 stages x 9216 floats
    cudaFuncSetAttribute(gemm_mma, cudaFuncAttributeMaxDynamicSharedMemorySize, gemm_smem);
    gemm_mma<<<dim3(Ss / 128, D3 / 128, Nn), 512, gemm_smem>>>(bqkv, nullptr, nullptr, 0);

    cudaFuncSetAttribute(attn_mma, cudaFuncAttributeMaxDynamicSharedMemorySize, ATT_SMEM);
    attn_mma<<<dim3(Ss / 128, Nn * NHEADS), 256, ATT_SMEM>>>();

    gemm_mma<<<dim3(Ss / 128, Cc / 128, Nn), 512, gemm_smem>>>(bout, x, out, 1);
}

// round 8
// speedup vs baseline: 1.4419x; 1.0168x over previous
#include <cuda_runtime.h>
#include <math.h>
#include <stdint.h>

// ---------------------------------------------------------------------------
// Problem constants
// ---------------------------------------------------------------------------
#define Nn 16            // B*T
#define Cc 512
#define Ss 1024          // H*W
#define NHEADS 8
#define HD 64
#define D3 1536          // 3*C

// ---------------------------------------------------------------------------
// Scratch (device globals; no cudaMalloc allowed)
// ---------------------------------------------------------------------------
__device__ float g_hn   [Nn * Ss * Cc];           // [n][s][c] tf32
__device__ float g_q    [Nn * NHEADS * Ss * HD];  // [nh][s][e] tf32
__device__ float g_k    [Nn * NHEADS * Ss * HD];  // [nh][s][e] tf32
__device__ float g_v    [Nn * NHEADS * HD * Ss];  // [nh][e][s] tf32
__device__ float g_att  [Nn * Ss * Cc];           // [n][s][c] tf32
__device__ float g_wqkvT[D3 * Cc];                // [d][c] tf32
__device__ float g_woutT[Cc * Cc];                // [c2][c] tf32

// ---------------------------------------------------------------------------
// Helpers
// ---------------------------------------------------------------------------
__device__ __forceinline__ uint32_t smem_u32(const void* p) {
    uint32_t a;
    asm("{ .reg .u64 t; cvta.to.shared.u64 t, %1; cvt.u32.u64 %0, t; }"
        : "=r"(a) : "l"(p));
    return a;
}

__device__ __forceinline__ float tf32r(float x) {
    uint32_t u;
    asm("cvt.rna.tf32.f32 %0, %1;" : "=r"(u) : "f"(x));
    return __uint_as_float(u);
}

// m16n8k8 tf32 mma, D = A*B + D (in place)
__device__ __forceinline__ void mma8(float* d, const uint32_t* a, const uint32_t* b) {
    asm volatile(
        "mma.sync.aligned.m16n8k8.row.col.f32.tf32.tf32.f32 "
        "{%0,%1,%2,%3}, {%4,%5,%6,%7}, {%8,%9}, {%0,%1,%2,%3};"
        : "+f"(d[0]), "+f"(d[1]), "+f"(d[2]), "+f"(d[3])
        : "r"(a[0]), "r"(a[1]), "r"(a[2]), "r"(a[3]), "r"(b[0]), "r"(b[1]));
}

__device__ __forceinline__ void cp16(uint32_t dst, const void* src) {
    asm volatile("cp.async.cg.shared.global [%0], [%1], 16;" :: "r"(dst), "l"(src));
}
#define CP_COMMIT() asm volatile("cp.async.commit_group;" ::: "memory")
#define CP_WAIT1()  asm volatile("cp.async.wait_group 1;" ::: "memory")

// ---------------------------------------------------------------------------
// Kernel 0: weight transpose + tf32 rounding   in [512][Ccols] -> out [Ccols][512]
// ---------------------------------------------------------------------------
__global__ void __launch_bounds__(256) trans_kernel(const float* __restrict__ in,
                                                    int Ccols, int which)
{
    float* out = which ? g_woutT : g_wqkvT;
    __shared__ float t[32][33];
    int c0 = blockIdx.x * 32, r0 = blockIdx.y * 32;
    int tx = threadIdx.x, ty = threadIdx.y;
#pragma unroll
    for (int i = 0; i < 32; i += 8)
        t[ty + i][tx] = in[(size_t)(r0 + ty + i) * Ccols + c0 + tx];
    __syncthreads();
#pragma unroll
    for (int i = 0; i < 32; i += 8)
        out[(size_t)(c0 + ty + i) * 512 + r0 + tx] = tf32r(t[tx][ty + i]);
}

// ---------------------------------------------------------------------------
// Kernel 1: GroupNorm (32 groups, eps=1e-6) -> g_hn [n][s][c] (tf32)
// ---------------------------------------------------------------------------
__global__ void __launch_bounds__(256) gn_kernel(const float* __restrict__ x,
                                                 const float* __restrict__ sc,
                                                 const float* __restrict__ bi)
{
    extern __shared__ float smt[];   // [1024][17]
    int n = blockIdx.x >> 5;
    int g = blockIdx.x & 31;
    const float* px = x + (size_t)(n * Cc + g * 16) * Ss;
    float* ph = g_hn + (size_t)n * Ss * Cc + g * 16;
    int tid = threadIdx.x;
    const int M = 16 * Ss;

    float s = 0.f, ss = 0.f;
    for (int i = tid * 4; i < M; i += 1024) {
        float4 v = *(const float4*)&px[i];
        s  += v.x + v.y + v.z + v.w;
        ss += v.x*v.x + v.y*v.y + v.z*v.z + v.w*v.w;
    }
#pragma unroll
    for (int o = 16; o; o >>= 1) {
        s  += __shfl_xor_sync(0xffffffffu, s,  o);
        ss += __shfl_xor_sync(0xffffffffu, ss, o);
    }
    __shared__ float r0[8], r1[8];
    __shared__ float s_mean, s_inv;
    if ((tid & 31) == 0) { r0[tid >> 5] = s; r1[tid >> 5] = ss; }
    __syncthreads();
    if (tid == 0) {
        float a = 0.f, b2 = 0.f;
#pragma unroll
        for (int i = 0; i < 8; i++) { a += r0[i]; b2 += r1[i]; }
        float mean = a / (float)M;
        float var  = b2 / (float)M - mean * mean;
        s_mean = mean;
        s_inv  = rsqrtf(var + 1e-6f);
    }
    __syncthreads();
    float mean = s_mean, inv = s_inv;

    for (int i = tid * 4; i < M; i += 1024) {
        int c  = i >> 10;
        int sp = i & 1023;
        float scv = sc[g * 16 + c] * inv;
        float biv = bi[g * 16 + c] - mean * scv;
        float4 v = *(const float4*)&px[i];
        smt[(sp + 0) * 17 + c] = tf32r(v.x * scv + biv);
        smt[(sp + 1) * 17 + c] = tf32r(v.y * scv + biv);
        smt[(sp + 2) * 17 + c] = tf32r(v.z * scv + biv);
        smt[(sp + 3) * 17 + c] = tf32r(v.w * scv + biv);
    }
    __syncthreads();

#pragma unroll
    for (int j = 0; j < 4; j++) {
        int sp = tid * 4 + j;
        const float* row = &smt[sp * 17];
        float* dst = ph + (size_t)sp * Cc;
#pragma unroll
        for (int q = 0; q < 4; q++) {
            float4 o = make_float4(row[q*4+0], row[q*4+1], row[q*4+2], row[q*4+3]);
            *(float4*)&dst[q * 4] = o;
        }
    }
}

// ---------------------------------------------------------------------------
// Kernel 2: tf32 mma.sync GEMM, tile 128x128, K=512, BK=32, 3-stage cp.async.
// 128 threads = 4 warps as 2(M) x 2(N); warp tile 64x64 -> 128 accum regs.
// Fat warps minimize smem fragment traffic (crossbar-bound regime).
// ---------------------------------------------------------------------------
__device__ __forceinline__ void gemm_load(uint32_t sbase, int soff,
                                          const float* __restrict__ Ag,
                                          const float* __restrict__ Bg,
                                          int koff, int tid)
{
#pragma unroll
    for (int i = 0; i < 8; i++) {
        int f = tid + i * 128;
        int row = f >> 3, c4 = f & 7;
        cp16(sbase + (uint32_t)((soff + row * 36 + c4 * 4) * 4),
             Ag + (size_t)row * Cc + koff + c4 * 4);
        cp16(sbase + (uint32_t)((soff + 4608 + row * 36 + c4 * 4) * 4),
             Bg + (size_t)row * Cc + koff + c4 * 4);
    }
}

__global__ void __launch_bounds__(128, 2) gemm_mma(const float* __restrict__ bias,
                                                   const float* __restrict__ xres,
                                                   float* __restrict__ out,
                                                   int mode)
{
    extern __shared__ float sm[];
    uint32_t sbase = smem_u32(sm);
    int tid = threadIdx.x, lane = tid & 31, wid = tid >> 5;
    int g = lane >> 2, tg = lane & 3;
    int n = blockIdx.z, s0 = blockIdx.x * 128, d0 = blockIdx.y * 128;
    int wm = wid & 1, wn = wid >> 1;

    const float* Ag = (mode ? g_att : g_hn) + ((size_t)n * Ss + s0) * Cc;
    const float* Bg = (mode ? g_woutT : g_wqkvT) + (size_t)d0 * Cc;

    float C[4][8][4] = {};

    gemm_load(sbase, 0, Ag, Bg, 0, tid);
    CP_COMMIT();
    gemm_load(sbase, 9216, Ag, Bg, 32, tid);
    CP_COMMIT();

    for (int kc = 0; kc < 16; kc++) {
        CP_WAIT1();
        __syncthreads();
        int b = kc % 3;
        if (kc + 2 < 16)
            gemm_load(sbase, ((kc + 2) % 3) * 9216, Ag, Bg, (kc + 2) * 32, tid);
        CP_COMMIT();

        const float* As = sm + b * 9216;
        const float* Bs = As + 4608;
#pragma unroll
        for (int ks = 0; ks < 4; ks++) {
            int k0 = ks * 8;
            uint32_t a[4][4];
#pragma unroll
            for (int tm = 0; tm < 4; tm++) {
                int r = wm * 64 + tm * 16 + g;
                a[tm][0] = __float_as_uint(As[r * 36 + k0 + tg]);
                a[tm][1] = __float_as_uint(As[(r + 8) * 36 + k0 + tg]);
                a[tm][2] = __float_as_uint(As[r * 36 + k0 + tg + 4]);
                a[tm][3] = __float_as_uint(As[(r + 8) * 36 + k0 + tg + 4]);
            }
#pragma unroll
            for (int tn = 0; tn < 8; tn++) {
                int c = wn * 64 + tn * 8 + g;
                uint32_t bb[2];
                bb[0] = __float_as_uint(Bs[c * 36 + k0 + tg]);
                bb[1] = __float_as_uint(Bs[c * 36 + k0 + tg + 4]);
#pragma unroll
                for (int tm = 0; tm < 4; tm++)
                    mma8(C[tm][tn], a[tm], bb);
            }
        }
    }

    // epilogue
#pragma unroll
    for (int tm = 0; tm < 4; tm++) {
#pragma unroll
        for (int hh = 0; hh < 2; hh++) {
            int m = s0 + wm * 64 + tm * 16 + g + hh * 8;
#pragma unroll
            for (int tn = 0; tn < 8; tn++) {
                int d = d0 + wn * 64 + tn * 8 + 2 * tg;
                float v0 = C[tm][tn][hh * 2 + 0] + __ldg(&bias[d]);
                float v1 = C[tm][tn][hh * 2 + 1] + __ldg(&bias[d + 1]);
                if (mode == 0) {
                    int head = d / 192, t = d % 192;
                    int part = t >> 6, e = t & 63;
                    size_t nh = (size_t)(n * 8 + head);
                    if (part == 0) {
                        float2 val = make_float2(tf32r(v0), tf32r(v1));
                        *(float2*)&g_q[(nh * Ss + m) * HD + e] = val;
                    } else if (part == 1) {
                        float2 val = make_float2(tf32r(v0), tf32r(v1));
                        *(float2*)&g_k[(nh * Ss + m) * HD + e] = val;
                    } else {
                        g_v[(nh * HD + e) * Ss + m]     = tf32r(v0);
                        g_v[(nh * HD + e + 1) * Ss + m] = tf32r(v1);
                    }
                } else {
                    size_t gi = ((size_t)n * Cc + d) * Ss + m;
                    out[gi]      = v0 + xres[gi];
                    out[gi + Ss] = v1 + xres[gi + Ss];
                }
            }
        }
    }
}

// ---------------------------------------------------------------------------
// Kernel 3: flash attention, tf32 mma.sync, double-buffered cp.async K/V,
// shuffle-transposed P. 128 threads = 4 warps, each owning 32 q rows.
// SMEM floats: KV stage b: K at b*8704, V at b*8704+4352; Q at 17408.
// ---------------------------------------------------------------------------
#define ATT_SMEM 104448

__device__ __forceinline__ void attn_load_kv(uint32_t sbase, int b,
                                             const float* __restrict__ K,
                                             const float* __restrict__ V,
                                             int kt, int tid)
{
#pragma unroll
    for (int i = 0; i < 8; i++) {
        int f = tid + i * 128;
        int r = f >> 4, c4 = f & 15;
        cp16(sbase + (uint32_t)((b * 8704 + r * 68 + c4 * 4) * 4),
             K + (size_t)(kt * 64 + r) * HD + c4 * 4);
        cp16(sbase + (uint32_t)((b * 8704 + 4352 + r * 68 + c4 * 4) * 4),
             V + (size_t)r * Ss + kt * 64 + c4 * 4);
    }
}

__global__ void __launch_bounds__(128, 2) attn_mma()
{
    extern __shared__ float sm[];
    uint32_t sbase = smem_u32(sm);
    float* Qs = sm + 17408;

    int tid = threadIdx.x, lane = tid & 31, w = tid >> 5;
    int g = lane >> 2, tg = lane & 3;
    int nh = blockIdx.y, q0 = blockIdx.x * 128;
    const float* Q = g_q + (size_t)nh * Ss * HD;
    const float* K = g_k + (size_t)nh * Ss * HD;
    const float* V = g_v + (size_t)nh * HD * Ss;

    // prologue: Q + KV(0) -> group 0; KV(1) -> group 1
#pragma unroll
    for (int i = 0; i < 16; i++) {
        int f = tid + i * 128;
        int row = f >> 4, c4 = f & 15;
        cp16(sbase + (uint32_t)((17408 + row * 68 + c4 * 4) * 4),
             Q + (size_t)(q0 + row) * HD + c4 * 4);
    }
    attn_load_kv(sbase, 0, K, V, 0, tid);
    CP_COMMIT();
    attn_load_kv(sbase, 1, K, V, 1, tid);
    CP_COMMIT();

    float S[2][8][4], O[2][8][4] = {};
    float mm[4] = {-1e30f, -1e30f, -1e30f, -1e30f};
    float ll[4] = {0.f, 0.f, 0.f, 0.f};
    int qb = w * 32;
    int srcA = g * 4 + (tg >> 1);
    int srcB = srcA + 2;
    bool oddc = (tg & 1);

    for (int kt = 0; kt < 16; kt++) {
        CP_WAIT1();
        __syncthreads();
        int b = kt & 1;
        const float* Ks = sm + b * 8704;
        const float* Vs = Ks + 4352;

        // S = Q @ K^T (warp: 32 q rows x 64 keys)
#pragma unroll
        for (int tm = 0; tm < 2; tm++)
#pragma unroll
            for (int tn = 0; tn < 8; tn++)
#pragma unroll
                for (int r = 0; r < 4; r++) S[tm][tn][r] = 0.f;
#pragma unroll
        for (int ks = 0; ks < 8; ks++) {
            int k0 = ks * 8;
            uint32_t a[2][4];
#pragma unroll
            for (int tm = 0; tm < 2; tm++) {
                int r = qb + tm * 16 + g;
                a[tm][0] = __float_as_uint(Qs[r * 68 + k0 + tg]);
                a[tm][1] = __float_as_uint(Qs[(r + 8) * 68 + k0 + tg]);
                a[tm][2] = __float_as_uint(Qs[r * 68 + k0 + tg + 4]);
                a[tm][3] = __float_as_uint(Qs[(r + 8) * 68 + k0 + tg + 4]);
            }
#pragma unroll
            for (int tn = 0; tn < 8; tn++) {
                uint32_t bfr[2];
                bfr[0] = __float_as_uint(Ks[(tn * 8 + g) * 68 + k0 + tg]);
                bfr[1] = __float_as_uint(Ks[(tn * 8 + g) * 68 + k0 + tg + 4]);
                mma8(S[0][tn], a[0], bfr);
                mma8(S[1][tn], a[1], bfr);
            }
        }

        // scale + online softmax (per 16-row m-tile)
#pragma unroll
        for (int tm = 0; tm < 2; tm++) {
            float mx0 = -1e30f, mx1 = -1e30f;
#pragma unroll
            for (int tn = 0; tn < 8; tn++) {
                S[tm][tn][0] *= 0.125f; S[tm][tn][1] *= 0.125f;
                S[tm][tn][2] *= 0.125f; S[tm][tn][3] *= 0.125f;
                mx0 = fmaxf(mx0, fmaxf(S[tm][tn][0], S[tm][tn][1]));
                mx1 = fmaxf(mx1, fmaxf(S[tm][tn][2], S[tm][tn][3]));
            }
            mx0 = fmaxf(mx0, __shfl_xor_sync(0xffffffffu, mx0, 1));
            mx0 = fmaxf(mx0, __shfl_xor_sync(0xffffffffu, mx0, 2));
            mx1 = fmaxf(mx1, __shfl_xor_sync(0xffffffffu, mx1, 1));
            mx1 = fmaxf(mx1, __shfl_xor_sync(0xffffffffu, mx1, 2));
            float mn0 = fmaxf(mm[tm * 2], mx0), mn1 = fmaxf(mm[tm * 2 + 1], mx1);
            float cr0 = __expf(mm[tm * 2] - mn0), cr1 = __expf(mm[tm * 2 + 1] - mn1);
            float rs0 = 0.f, rs1 = 0.f;
#pragma unroll
            for (int tn = 0; tn < 8; tn++) {
                S[tm][tn][0] = tf32r(__expf(S[tm][tn][0] - mn0));
                S[tm][tn][1] = tf32r(__expf(S[tm][tn][1] - mn0));
                S[tm][tn][2] = tf32r(__expf(S[tm][tn][2] - mn1));
                S[tm][tn][3] = tf32r(__expf(S[tm][tn][3] - mn1));
                rs0 += S[tm][tn][0] + S[tm][tn][1];
                rs1 += S[tm][tn][2] + S[tm][tn][3];
            }
            rs0 += __shfl_xor_sync(0xffffffffu, rs0, 1);
            rs0 += __shfl_xor_sync(0xffffffffu, rs0, 2);
            rs1 += __shfl_xor_sync(0xffffffffu, rs1, 1);
            rs1 += __shfl_xor_sync(0xffffffffu, rs1, 2);
            ll[tm * 2]     = ll[tm * 2] * cr0 + rs0;
            ll[tm * 2 + 1] = ll[tm * 2 + 1] * cr1 + rs1;
            mm[tm * 2] = mn0;  mm[tm * 2 + 1] = mn1;
#pragma unroll
            for (int tn = 0; tn < 8; tn++) {
                O[tm][tn][0] *= cr0; O[tm][tn][1] *= cr0;
                O[tm][tn][2] *= cr1; O[tm][tn][3] *= cr1;
            }
        }

        // O += P @ V (P a-frags via quad shuffles)
#pragma unroll
        for (int ks = 0; ks < 8; ks++) {
            int k0 = ks * 8;
            uint32_t a[2][4];
#pragma unroll
            for (int tm = 0; tm < 2; tm++) {
                float e00 = __shfl_sync(0xffffffffu, S[tm][ks][0], srcA);
                float e01 = __shfl_sync(0xffffffffu, S[tm][ks][1], srcA);
                float e10 = __shfl_sync(0xffffffffu, S[tm][ks][2], srcA);
                float e11 = __shfl_sync(0xffffffffu, S[tm][ks][3], srcA);
                float f00 = __shfl_sync(0xffffffffu, S[tm][ks][0], srcB);
                float f01 = __shfl_sync(0xffffffffu, S[tm][ks][1], srcB);
                float f10 = __shfl_sync(0xffffffffu, S[tm][ks][2], srcB);
                float f11 = __shfl_sync(0xffffffffu, S[tm][ks][3], srcB);
                a[tm][0] = __float_as_uint(oddc ? e01 : e00);
                a[tm][1] = __float_as_uint(oddc ? e11 : e10);
                a[tm][2] = __float_as_uint(oddc ? f01 : f00);
                a[tm][3] = __float_as_uint(oddc ? f11 : f10);
            }
#pragma unroll
            for (int tn = 0; tn < 8; tn++) {
                uint32_t bfr[2];
                bfr[0] = __float_as_uint(Vs[(tn * 8 + g) * 68 + k0 + tg]);
                bfr[1] = __float_as_uint(Vs[(tn * 8 + g) * 68 + k0 + tg + 4]);
                mma8(O[0][tn], a[0], bfr);
                mma8(O[1][tn], a[1], bfr);
            }
        }

        __syncthreads();
        if (kt + 2 < 16)
            attn_load_kv(sbase, b, K, V, kt + 2, tid);
        CP_COMMIT();
    }

    // epilogue -> g_att[n][s][head*64 + e], tf32-rounded
    int n = nh >> 3, head = nh & 7;
    float* dst = g_att + (size_t)n * Ss * Cc + head * 64;
#pragma unroll
    for (int tm = 0; tm < 2; tm++) {
        float inv0 = 1.f / ll[tm * 2], inv1 = 1.f / ll[tm * 2 + 1];
        int srow0 = q0 + qb + tm * 16 + g, srow1 = srow0 + 8;
#pragma unroll
        for (int tn = 0; tn < 8; tn++) {
            int c = tn * 8 + 2 * tg;
            float2 v0 = make_float2(tf32r(O[tm][tn][0] * inv0), tf32r(O[tm][tn][1] * inv0));
            float2 v1 = make_float2(tf32r(O[tm][tn][2] * inv1), tf32r(O[tm][tn][3] * inv1));
            *(float2*)&dst[(size_t)srow0 * Cc + c] = v0;
            *(float2*)&dst[(size_t)srow1 * Cc + c] = v1;
        }
    }
}

// ---------------------------------------------------------------------------
extern "C" void kernel_launch(void* const* d_in, const int* in_sizes, int n_in,
                              void* d_out, int out_size)
{
    const float* x    = (const float*)d_in[0];
    const float* gsc  = (const float*)d_in[1];
    const float* gbi  = (const float*)d_in[2];
    const float* wqkv = (const float*)d_in[3];
    const float* bqkv = (const float*)d_in[4];
    const float* wout = (const float*)d_in[5];
    const float* bout = (const float*)d_in[6];
    float* out = (float*)d_out;

    trans_kernel<<<dim3(D3 / 32, Cc / 32), dim3(32, 8)>>>(wqkv, D3, 0);
    trans_kernel<<<dim3(Cc / 32, Cc / 32), dim3(32, 8)>>>(wout, Cc, 1);

    cudaFuncSetAttribute(gn_kernel, cudaFuncAttributeMaxDynamicSharedMemorySize, 69632);
    gn_kernel<<<Nn * 32, 256, 69632>>>(x, gsc, gbi);

    const int gemm_smem = 27648 * 4;   // 3 stages x 9216 floats
    cudaFuncSetAttribute(gemm_mma, cudaFuncAttributeMaxDynamicSharedMemorySize, gemm_smem);
    gemm_mma<<<dim3(Ss / 128, D3 / 128, Nn), 128, gemm_smem>>>(bqkv, nullptr, nullptr, 0);

    cudaFuncSetAttribute(attn_mma, cudaFuncAttributeMaxDynamicSharedMemorySize, ATT_SMEM);
    attn_mma<<<dim3(Ss / 128, Nn * NHEADS), 128, ATT_SMEM>>>();

    gemm_mma<<<dim3(Ss / 128, Cc / 128, Nn), 128, gemm_smem>>>(bout, x, out, 1);
}

// round 9
// speedup vs baseline: 2.3491x; 1.6292x over previous
#include <cuda_runtime.h>
#include <cuda_bf16.h>
#include <math.h>
#include <stdint.h>

// ---------------------------------------------------------------------------
// Problem constants
// ---------------------------------------------------------------------------
#define Nn 16            // B*T
#define Cc 512
#define Ss 1024          // H*W
#define NHEADS 8
#define HD 64
#define D3 1536          // 3*C

typedef __nv_bfloat16 bf16;

// ---------------------------------------------------------------------------
// Scratch (device globals; no cudaMalloc allowed)
// ---------------------------------------------------------------------------
__device__ bf16 g_hn   [Nn * Ss * Cc];           // [n][s][c]
__device__ bf16 g_q    [Nn * NHEADS * Ss * HD];  // [nh][s][e]
__device__ bf16 g_k    [Nn * NHEADS * Ss * HD];  // [nh][s][e]
__device__ bf16 g_v    [Nn * NHEADS * HD * Ss];  // [nh][e][s] (transposed)
__device__ bf16 g_att  [Nn * Ss * Cc];           // [n][s][c]
__device__ bf16 g_wqkvT[D3 * Cc];                // [d][c]
__device__ bf16 g_woutT[Cc * Cc];                // [c2][c]

// ---------------------------------------------------------------------------
// Helpers
// ---------------------------------------------------------------------------
__device__ __forceinline__ uint32_t smem_u32(const void* p) {
    uint32_t a;
    asm("{ .reg .u64 t; cvta.to.shared.u64 t, %1; cvt.u32.u64 %0, t; }"
        : "=r"(a) : "l"(p));
    return a;
}

// pack two fp32 -> bf16x2 (lo = first arg)
__device__ __forceinline__ uint32_t packbf(float lo, float hi) {
    uint32_t r;
    asm("cvt.rn.bf16x2.f32 %0, %1, %2;" : "=r"(r) : "f"(hi), "f"(lo));
    return r;
}

// m16n8k16 bf16 mma, D = A*B + D (in place), fp32 accumulate
__device__ __forceinline__ void mma16(float* d, const uint32_t* a, const uint32_t* b) {
    asm volatile(
        "mma.sync.aligned.m16n8k16.row.col.f32.bf16.bf16.f32 "
        "{%0,%1,%2,%3}, {%4,%5,%6,%7}, {%8,%9}, {%0,%1,%2,%3};"
        : "+f"(d[0]), "+f"(d[1]), "+f"(d[2]), "+f"(d[3])
        : "r"(a[0]), "r"(a[1]), "r"(a[2]), "r"(a[3]), "r"(b[0]), "r"(b[1]));
}

__device__ __forceinline__ void cp16(uint32_t dst, const void* src) {
    asm volatile("cp.async.cg.shared.global [%0], [%1], 16;" :: "r"(dst), "l"(src));
}
#define CP_COMMIT() asm volatile("cp.async.commit_group;" ::: "memory")
#define CP_WAIT1()  asm volatile("cp.async.wait_group 1;" ::: "memory")

// ---------------------------------------------------------------------------
// Kernel 0: weight transpose + bf16 rounding   in [512][Ccols] -> out [Ccols][512]
// ---------------------------------------------------------------------------
__global__ void __launch_bounds__(256) trans_kernel(const float* __restrict__ in,
                                                    int Ccols, int which)
{
    bf16* out = which ? g_woutT : g_wqkvT;
    __shared__ float t[32][33];
    int c0 = blockIdx.x * 32, r0 = blockIdx.y * 32;
    int tx = threadIdx.x, ty = threadIdx.y;
#pragma unroll
    for (int i = 0; i < 32; i += 8)
        t[ty + i][tx] = in[(size_t)(r0 + ty + i) * Ccols + c0 + tx];
    __syncthreads();
#pragma unroll
    for (int i = 0; i < 32; i += 8)
        out[(size_t)(c0 + ty + i) * 512 + r0 + tx] = __float2bfloat16_rn(t[tx][ty + i]);
}

// ---------------------------------------------------------------------------
// Kernel 1: GroupNorm (32 groups, eps=1e-6) -> g_hn [n][s][c] (bf16)
// ---------------------------------------------------------------------------
__global__ void __launch_bounds__(256) gn_kernel(const float* __restrict__ x,
                                                 const float* __restrict__ sc,
                                                 const float* __restrict__ bi)
{
    extern __shared__ float smt[];   // [1024][17]
    int n = blockIdx.x >> 5;
    int g = blockIdx.x & 31;
    const float* px = x + (size_t)(n * Cc + g * 16) * Ss;
    bf16* ph = g_hn + (size_t)n * Ss * Cc + g * 16;
    int tid = threadIdx.x;
    const int M = 16 * Ss;

    float s = 0.f, ss = 0.f;
    for (int i = tid * 4; i < M; i += 1024) {
        float4 v = *(const float4*)&px[i];
        s  += v.x + v.y + v.z + v.w;
        ss += v.x*v.x + v.y*v.y + v.z*v.z + v.w*v.w;
    }
#pragma unroll
    for (int o = 16; o; o >>= 1) {
        s  += __shfl_xor_sync(0xffffffffu, s,  o);
        ss += __shfl_xor_sync(0xffffffffu, ss, o);
    }
    __shared__ float r0[8], r1[8];
    __shared__ float s_mean, s_inv;
    if ((tid & 31) == 0) { r0[tid >> 5] = s; r1[tid >> 5] = ss; }
    __syncthreads();
    if (tid == 0) {
        float a = 0.f, b2 = 0.f;
#pragma unroll
        for (int i = 0; i < 8; i++) { a += r0[i]; b2 += r1[i]; }
        float mean = a / (float)M;
        float var  = b2 / (float)M - mean * mean;
        s_mean = mean;
        s_inv  = rsqrtf(var + 1e-6f);
    }
    __syncthreads();
    float mean = s_mean, inv = s_inv;

    for (int i = tid * 4; i < M; i += 1024) {
        int c  = i >> 10;
        int sp = i & 1023;
        float scv = sc[g * 16 + c] * inv;
        float biv = bi[g * 16 + c] - mean * scv;
        float4 v = *(const float4*)&px[i];
        smt[(sp + 0) * 17 + c] = v.x * scv + biv;
        smt[(sp + 1) * 17 + c] = v.y * scv + biv;
        smt[(sp + 2) * 17 + c] = v.z * scv + biv;
        smt[(sp + 3) * 17 + c] = v.w * scv + biv;
    }
    __syncthreads();

    // write 16-bf16 rows (32 B = 2 x 16B stores)
#pragma unroll
    for (int j = 0; j < 4; j++) {
        int sp = tid * 4 + j;
        const float* row = &smt[sp * 17];
        uint32_t pk[8];
#pragma unroll
        for (int q = 0; q < 8; q++) pk[q] = packbf(row[2*q], row[2*q+1]);
        uint4* dst = (uint4*)(ph + (size_t)sp * Cc);
        dst[0] = make_uint4(pk[0], pk[1], pk[2], pk[3]);
        dst[1] = make_uint4(pk[4], pk[5], pk[6], pk[7]);
    }
}

// ---------------------------------------------------------------------------
// Kernel 2: bf16 m16n8k16 GEMM, tile 128x128, K=512, BK=32, 3-stage cp.async.
// 256 threads = 8 warps as 4(M) x 2(N); warp tile 32x64.
// SMEM: bf16, row stride 40 (80 B) => conflict-free fragment loads.
// Stage = (128*40)*2 matrices * 2B = 20480 B; 3 stages = 61440 B.
// ---------------------------------------------------------------------------
__device__ __forceinline__ void gemm_load(uint32_t sbase, int soff,
                                          const bf16* __restrict__ Ag,
                                          const bf16* __restrict__ Bg,
                                          int koff, int tid)
{
#pragma unroll
    for (int i = 0; i < 2; i++) {
        int f = tid + i * 256;
        int row = f >> 2, c = f & 3;          // 4 x 16B chunks per 32-bf16 row
        cp16(sbase + (uint32_t)(soff + row * 80 + c * 16),
             Ag + (size_t)row * Cc + koff + c * 8);
        cp16(sbase + (uint32_t)(soff + 10240 + row * 80 + c * 16),
             Bg + (size_t)row * Cc + koff + c * 8);
    }
}

__global__ void __launch_bounds__(256, 2) gemm_mma(const float* __restrict__ bias,
                                                   const float* __restrict__ xres,
                                                   float* __restrict__ out,
                                                   int mode)
{
    extern __shared__ char smc[];
    uint32_t sbase = smem_u32(smc);
    int tid = threadIdx.x, lane = tid & 31, wid = tid >> 5;
    int g = lane >> 2, tg = lane & 3;
    int n = blockIdx.z, s0 = blockIdx.x * 128, d0 = blockIdx.y * 128;
    int wm = wid & 3, wn = wid >> 2;

    const bf16* Ag = (mode ? g_att : g_hn) + ((size_t)n * Ss + s0) * Cc;
    const bf16* Bg = (mode ? g_woutT : g_wqkvT) + (size_t)d0 * Cc;

    float C[2][8][4] = {};

    gemm_load(sbase, 0, Ag, Bg, 0, tid);
    CP_COMMIT();
    gemm_load(sbase, 20480, Ag, Bg, 32, tid);
    CP_COMMIT();

    for (int kc = 0; kc < 16; kc++) {
        CP_WAIT1();
        __syncthreads();
        int b = kc % 3;
        if (kc + 2 < 16)
            gemm_load(sbase, ((kc + 2) % 3) * 20480, Ag, Bg, (kc + 2) * 32, tid);
        CP_COMMIT();

        const bf16* As = (const bf16*)(smc + b * 20480);
        const bf16* Bs = (const bf16*)(smc + b * 20480 + 10240);
#pragma unroll
        for (int ks = 0; ks < 2; ks++) {       // two k16 steps per BK=32
            int k0 = ks * 16;
            uint32_t a[2][4], bb[8][2];
#pragma unroll
            for (int tm = 0; tm < 2; tm++) {
                int r = wm * 32 + tm * 16 + g;
                a[tm][0] = *(const uint32_t*)&As[r * 40 + k0 + 2 * tg];
                a[tm][1] = *(const uint32_t*)&As[(r + 8) * 40 + k0 + 2 * tg];
                a[tm][2] = *(const uint32_t*)&As[r * 40 + k0 + 2 * tg + 8];
                a[tm][3] = *(const uint32_t*)&As[(r + 8) * 40 + k0 + 2 * tg + 8];
            }
#pragma unroll
            for (int tn = 0; tn < 8; tn++) {
                int c = wn * 64 + tn * 8 + g;
                bb[tn][0] = *(const uint32_t*)&Bs[c * 40 + k0 + 2 * tg];
                bb[tn][1] = *(const uint32_t*)&Bs[c * 40 + k0 + 2 * tg + 8];
            }
#pragma unroll
            for (int tm = 0; tm < 2; tm++)
#pragma unroll
                for (int tn = 0; tn < 8; tn++)
                    mma16(C[tm][tn], a[tm], bb[tn]);
        }
    }

    // epilogue
#pragma unroll
    for (int tm = 0; tm < 2; tm++) {
#pragma unroll
        for (int hh = 0; hh < 2; hh++) {
            int m = s0 + wm * 32 + tm * 16 + g + hh * 8;
#pragma unroll
            for (int tn = 0; tn < 8; tn++) {
                int d = d0 + wn * 64 + tn * 8 + 2 * tg;
                float v0 = C[tm][tn][hh * 2 + 0] + __ldg(&bias[d]);
                float v1 = C[tm][tn][hh * 2 + 1] + __ldg(&bias[d + 1]);
                if (mode == 0) {
                    int head = d / 192, t = d % 192;
                    int part = t >> 6, e = t & 63;
                    size_t nh = (size_t)(n * 8 + head);
                    if (part == 0) {
                        *(uint32_t*)&g_q[(nh * Ss + m) * HD + e] = packbf(v0, v1);
                    } else if (part == 1) {
                        *(uint32_t*)&g_k[(nh * Ss + m) * HD + e] = packbf(v0, v1);
                    } else {
                        g_v[(nh * HD + e) * Ss + m]     = __float2bfloat16_rn(v0);
                        g_v[(nh * HD + e + 1) * Ss + m] = __float2bfloat16_rn(v1);
                    }
                } else {
                    size_t gi = ((size_t)n * Cc + d) * Ss + m;
                    out[gi]      = v0 + xres[gi];
                    out[gi + Ss] = v1 + xres[gi + Ss];
                }
            }
        }
    }
}

// ---------------------------------------------------------------------------
// Kernel 3: flash attention, bf16 m16n8k16, double-buffered cp.async K/V.
// P stays in registers: bf16 C-frag layout == A-frag layout (no shuffles).
// SMEM bytes: KV stage b: K at b*18432, V at +9216; Q at 36864. Total 55296.
// Row stride 72 bf16 (144 B) => conflict-free + 16B-aligned cp.async.
// ---------------------------------------------------------------------------
#define ATT_SMEM 55296

__device__ __forceinline__ void attn_load_kv(uint32_t sbase, int b,
                                             const bf16* __restrict__ K,
                                             const bf16* __restrict__ V,
                                             int kt, int tid)
{
#pragma unroll
    for (int i = 0; i < 2; i++) {
        int f = tid + i * 256;
        int r = f >> 3, c = f & 7;            // 8 x 16B chunks per 64-bf16 row
        cp16(sbase + (uint32_t)(b * 18432 + r * 144 + c * 16),
             K + (size_t)(kt * 64 + r) * HD + c * 8);
        cp16(sbase + (uint32_t)(b * 18432 + 9216 + r * 144 + c * 16),
             V + (size_t)r * Ss + kt * 64 + c * 8);
    }
}

__global__ void __launch_bounds__(256, 2) attn_mma()
{
    extern __shared__ char smc[];
    uint32_t sbase = smem_u32(smc);
    const bf16* Qs = (const bf16*)(smc + 36864);

    int tid = threadIdx.x, lane = tid & 31, w = tid >> 5;
    int g = lane >> 2, tg = lane & 3;
    int nh = blockIdx.y, q0 = blockIdx.x * 128;
    const bf16* Q = g_q + (size_t)nh * Ss * HD;
    const bf16* K = g_k + (size_t)nh * Ss * HD;
    const bf16* V = g_v + (size_t)nh * HD * Ss;

    // prologue: Q + KV(0) -> group 0; KV(1) -> group 1
#pragma unroll
    for (int i = 0; i < 4; i++) {
        int f = tid + i * 256;
        int row = f >> 3, c = f & 7;
        cp16(sbase + (uint32_t)(36864 + row * 144 + c * 16),
             Q + (size_t)(q0 + row) * HD + c * 8);
    }
    attn_load_kv(sbase, 0, K, V, 0, tid);
    CP_COMMIT();
    attn_load_kv(sbase, 1, K, V, 1, tid);
    CP_COMMIT();

    float O[8][4] = {};
    float m0 = -1e30f, m1 = -1e30f, l0 = 0.f, l1 = 0.f;
    int qb = w * 16;

    for (int kt = 0; kt < 16; kt++) {
        CP_WAIT1();
        __syncthreads();
        int b = kt & 1;
        const bf16* Ks = (const bf16*)(smc + b * 18432);
        const bf16* Vs = (const bf16*)(smc + b * 18432 + 9216);

        // S = Q @ K^T  (warp: 16 q rows x 64 keys), k-dim = e: 4 k16 steps
        float S[8][4] = {};
#pragma unroll
        for (int ks = 0; ks < 4; ks++) {
            int k0 = ks * 16;
            uint32_t a[4];
            a[0] = *(const uint32_t*)&Qs[(qb + g) * 72 + k0 + 2 * tg];
            a[1] = *(const uint32_t*)&Qs[(qb + g + 8) * 72 + k0 + 2 * tg];
            a[2] = *(const uint32_t*)&Qs[(qb + g) * 72 + k0 + 2 * tg + 8];
            a[3] = *(const uint32_t*)&Qs[(qb + g + 8) * 72 + k0 + 2 * tg + 8];
#pragma unroll
            for (int tn = 0; tn < 8; tn++) {
                uint32_t bfr[2];
                bfr[0] = *(const uint32_t*)&Ks[(tn * 8 + g) * 72 + k0 + 2 * tg];
                bfr[1] = *(const uint32_t*)&Ks[(tn * 8 + g) * 72 + k0 + 2 * tg + 8];
                mma16(S[tn], a, bfr);
            }
        }

        // scale + online softmax
        float mx0 = -1e30f, mx1 = -1e30f;
#pragma unroll
        for (int tn = 0; tn < 8; tn++) {
            S[tn][0] *= 0.125f; S[tn][1] *= 0.125f;
            S[tn][2] *= 0.125f; S[tn][3] *= 0.125f;
            mx0 = fmaxf(mx0, fmaxf(S[tn][0], S[tn][1]));
            mx1 = fmaxf(mx1, fmaxf(S[tn][2], S[tn][3]));
        }
        mx0 = fmaxf(mx0, __shfl_xor_sync(0xffffffffu, mx0, 1));
        mx0 = fmaxf(mx0, __shfl_xor_sync(0xffffffffu, mx0, 2));
        mx1 = fmaxf(mx1, __shfl_xor_sync(0xffffffffu, mx1, 1));
        mx1 = fmaxf(mx1, __shfl_xor_sync(0xffffffffu, mx1, 2));
        float mn0 = fmaxf(m0, mx0), mn1 = fmaxf(m1, mx1);
        float cr0 = __expf(m0 - mn0), cr1 = __expf(m1 - mn1);
        float rs0 = 0.f, rs1 = 0.f;
#pragma unroll
        for (int tn = 0; tn < 8; tn++) {
            S[tn][0] = __expf(S[tn][0] - mn0);
            S[tn][1] = __expf(S[tn][1] - mn0);
            S[tn][2] = __expf(S[tn][2] - mn1);
            S[tn][3] = __expf(S[tn][3] - mn1);
            rs0 += S[tn][0] + S[tn][1];
            rs1 += S[tn][2] + S[tn][3];
        }
        rs0 += __shfl_xor_sync(0xffffffffu, rs0, 1);
        rs0 += __shfl_xor_sync(0xffffffffu, rs0, 2);
        rs1 += __shfl_xor_sync(0xffffffffu, rs1, 1);
        rs1 += __shfl_xor_sync(0xffffffffu, rs1, 2);
        l0 = l0 * cr0 + rs0;  l1 = l1 * cr1 + rs1;
        m0 = mn0;  m1 = mn1;

        // pack P to bf16 (C-frag layout == A-frag layout: no shuffles!)
        uint32_t Pp[8][2];
#pragma unroll
        for (int tn = 0; tn < 8; tn++) {
            O[tn][0] *= cr0; O[tn][1] *= cr0;
            O[tn][2] *= cr1; O[tn][3] *= cr1;
            Pp[tn][0] = packbf(S[tn][0], S[tn][1]);   // row g,   cols 2tg,2tg+1
            Pp[tn][1] = packbf(S[tn][2], S[tn][3]);   // row g+8, cols 2tg,2tg+1
        }

        // O += P @ V : 4 k16 steps over j
#pragma unroll
        for (int ks = 0; ks < 4; ks++) {
            int k0 = ks * 16;
            uint32_t a[4];
            a[0] = Pp[2 * ks][0];        // row g,   j 16ks+2tg,+1
            a[1] = Pp[2 * ks][1];        // row g+8
            a[2] = Pp[2 * ks + 1][0];    // row g,   j 16ks+2tg+8,+9
            a[3] = Pp[2 * ks + 1][1];
#pragma unroll
            for (int tn = 0; tn < 8; tn++) {
                uint32_t bfr[2];
                bfr[0] = *(const uint32_t*)&Vs[(tn * 8 + g) * 72 + k0 + 2 * tg];
                bfr[1] = *(const uint32_t*)&Vs[(tn * 8 + g) * 72 + k0 + 2 * tg + 8];
                mma16(O[tn], a, bfr);
            }
        }

        __syncthreads();
        if (kt + 2 < 16)
            attn_load_kv(sbase, b, K, V, kt + 2, tid);
        CP_COMMIT();
    }

    // epilogue -> g_att[n][s][head*64 + e] (bf16 pairs)
    int n = nh >> 3, head = nh & 7;
    float inv0 = 1.f / l0, inv1 = 1.f / l1;
    int srow0 = q0 + qb + g, srow1 = srow0 + 8;
    bf16* dst = g_att + (size_t)n * Ss * Cc + head * 64;
#pragma unroll
    for (int tn = 0; tn < 8; tn++) {
        int c = tn * 8 + 2 * tg;
        *(uint32_t*)&dst[(size_t)srow0 * Cc + c] = packbf(O[tn][0] * inv0, O[tn][1] * inv0);
        *(uint32_t*)&dst[(size_t)srow1 * Cc + c] = packbf(O[tn][2] * inv1, O[tn][3] * inv1);
    }
}

// ---------------------------------------------------------------------------
extern "C" void kernel_launch(void* const* d_in, const int* in_sizes, int n_in,
                              void* d_out, int out_size)
{
    const float* x    = (const float*)d_in[0];
    const float* gsc  = (const float*)d_in[1];
    const float* gbi  = (const float*)d_in[2];
    const float* wqkv = (const float*)d_in[3];
    const float* bqkv = (const float*)d_in[4];
    const float* wout = (const float*)d_in[5];
    const float* bout = (const float*)d_in[6];
    float* out = (float*)d_out;

    trans_kernel<<<dim3(D3 / 32, Cc / 32), dim3(32, 8)>>>(wqkv, D3, 0);
    trans_kernel<<<dim3(Cc / 32, Cc / 32), dim3(32, 8)>>>(wout, Cc, 1);

    cudaFuncSetAttribute(gn_kernel, cudaFuncAttributeMaxDynamicSharedMemorySize, 69632);
    gn_kernel<<<Nn * 32, 256, 69632>>>(x, gsc, gbi);

    const int gemm_smem = 61440;   // 3 stages x 20480 B
    cudaFuncSetAttribute(gemm_mma, cudaFuncAttributeMaxDynamicSharedMemorySize, gemm_smem);
    gemm_mma<<<dim3(Ss / 128, D3 / 128, Nn), 256, gemm_smem>>>(bqkv, nullptr, nullptr, 0);

    cudaFuncSetAttribute(attn_mma, cudaFuncAttributeMaxDynamicSharedMemorySize, ATT_SMEM);
    attn_mma<<<dim3(Ss / 128, Nn * NHEADS), 256, ATT_SMEM>>>();

    gemm_mma<<<dim3(Ss / 128, Cc / 128, Nn), 256, gemm_smem>>>(bout, x, out, 1);
}